// round 1
// baseline (speedup 1.0000x reference)
#include <cuda_runtime.h>

// Problem dims (fixed by setup_inputs)
#define GM 1024   // B
#define GK 512    // IN
#define GN 2048   // D*P
#define DD 256    // D
#define PP 8      // P
#define TT 32     // NUM_STEPS

// Scratch for the projected currents I = x @ W_proj + b_proj  (8 MB)
__device__ float g_I[GM * GN];

// ---------------------------------------------------------------------------
// Kernel A: fp32 SGEMM, 128x128 tile, BK=8, 8x8 per thread, 256 threads.
// C[M,N] = A[M,K] @ B[K,N] + bias[N]
// ---------------------------------------------------------------------------
__global__ __launch_bounds__(256) void gemm_kernel(const float* __restrict__ A,
                                                   const float* __restrict__ B,
                                                   const float* __restrict__ bias) {
    const int BM = 128, BN = 128, BK = 8;
    __shared__ float As[BK][BM];   // transposed A tile
    __shared__ float Bs[BK][BN];

    const int tid = threadIdx.x;
    const int bx = blockIdx.x;     // N tile (16)
    const int by = blockIdx.y;     // M tile (8)

    // load mapping
    const int aRow = tid >> 1;            // 0..127
    const int aCol = (tid & 1) * 4;       // 0 or 4
    const int bRow = tid >> 5;            // 0..7
    const int bCol = (tid & 31) * 4;      // 0..124

    const float* Ab = A + (size_t)(by * BM) * GK;
    const float* Bb = B + bx * BN;

    const int ty = tid >> 4;   // 0..15
    const int tx = tid & 15;   // 0..15

    float acc[8][8];
#pragma unroll
    for (int i = 0; i < 8; i++)
#pragma unroll
        for (int j = 0; j < 8; j++) acc[i][j] = 0.f;

    for (int k0 = 0; k0 < GK; k0 += BK) {
        float4 av = *(const float4*)(Ab + (size_t)aRow * GK + k0 + aCol);
        As[aCol + 0][aRow] = av.x;
        As[aCol + 1][aRow] = av.y;
        As[aCol + 2][aRow] = av.z;
        As[aCol + 3][aRow] = av.w;
        float4 bv = *(const float4*)(Bb + (size_t)(k0 + bRow) * GN + bCol);
        *(float4*)&Bs[bRow][bCol] = bv;
        __syncthreads();

#pragma unroll
        for (int k = 0; k < BK; k++) {
            float ar[8], br[8];
            *(float4*)&ar[0] = *(const float4*)&As[k][ty * 8];
            *(float4*)&ar[4] = *(const float4*)&As[k][ty * 8 + 4];
            *(float4*)&br[0] = *(const float4*)&Bs[k][tx * 8];
            *(float4*)&br[4] = *(const float4*)&Bs[k][tx * 8 + 4];
#pragma unroll
            for (int i = 0; i < 8; i++)
#pragma unroll
                for (int j = 0; j < 8; j++)
                    acc[i][j] = fmaf(ar[i], br[j], acc[i][j]);
        }
        __syncthreads();
    }

#pragma unroll
    for (int i = 0; i < 8; i++) {
        const int row = by * BM + ty * 8 + i;
        const int col = bx * BN + tx * 8;
        float* outp = g_I + (size_t)row * GN + col;
#pragma unroll
        for (int j = 0; j < 8; j++)
            outp[j] = acc[i][j] + bias[col + j];
    }
}

// ---------------------------------------------------------------------------
// Kernel B: per-(b,d) cell: LIF recurrence (8 neurons x 32 steps) producing
// per-timestep spike bytes; rate branch + temporal conv branch via 256-entry
// LUTs in shared memory; fused output.
// ---------------------------------------------------------------------------
__global__ __launch_bounds__(256) void pop_kernel(
    const float* __restrict__ thr_g,    // [8]
    const float* __restrict__ rateW,    // [8]
    const float* __restrict__ rateB,    // [1]
    const float* __restrict__ c1w,      // [4][8][3]
    const float* __restrict__ c1b,      // [4]
    const float* __restrict__ c2w,      // [1][4][1] -> [4]
    const float* __restrict__ c2b,      // [1]
    const float* __restrict__ fusion,   // [2]
    float* __restrict__ out) {
    // LUTs: per 8-bit spike pattern m (bit p = neuron p spiked):
    //   lutK[m].c = sum_{p set} conv1_w[c][p][K]   (K = tap 0/1/2)
    //   conv1_b folded into center tap (tap 1).
    //   lutR[m]   = sum_{p set} rate_W[p]
    __shared__ float4 lut0[256], lut1[256], lut2[256];
    __shared__ float lutR[256];

    const int tid = threadIdx.x;
    {
        const int m = tid;
        float4 l0 = make_float4(0.f, 0.f, 0.f, 0.f);
        float4 l1 = make_float4(0.f, 0.f, 0.f, 0.f);
        float4 l2 = make_float4(0.f, 0.f, 0.f, 0.f);
        float r = 0.f;
#pragma unroll
        for (int p = 0; p < 8; p++) {
            if ((m >> p) & 1) {
                r += rateW[p];
                l0.x += c1w[0 * 24 + p * 3 + 0];
                l0.y += c1w[1 * 24 + p * 3 + 0];
                l0.z += c1w[2 * 24 + p * 3 + 0];
                l0.w += c1w[3 * 24 + p * 3 + 0];
                l1.x += c1w[0 * 24 + p * 3 + 1];
                l1.y += c1w[1 * 24 + p * 3 + 1];
                l1.z += c1w[2 * 24 + p * 3 + 1];
                l1.w += c1w[3 * 24 + p * 3 + 1];
                l2.x += c1w[0 * 24 + p * 3 + 2];
                l2.y += c1w[1 * 24 + p * 3 + 2];
                l2.z += c1w[2 * 24 + p * 3 + 2];
                l2.w += c1w[3 * 24 + p * 3 + 2];
            }
        }
        l1.x += c1b[0];
        l1.y += c1b[1];
        l1.z += c1b[2];
        l1.w += c1b[3];
        lut0[m] = l0;
        lut1[m] = l1;
        lut2[m] = l2;
        lutR[m] = r;
    }
    __syncthreads();

    const int cell = blockIdx.x * 256 + tid;   // b*D + d ; I base = cell*8

    const float4 i0 = *(const float4*)(g_I + (size_t)cell * 8);
    const float4 i1 = *(const float4*)(g_I + (size_t)cell * 8 + 4);
    float Iv[8] = {i0.x, i0.y, i0.z, i0.w, i1.x, i1.y, i1.z, i1.w};

    float thr[8];
#pragma unroll
    for (int p = 0; p < 8; p++) thr[p] = thr_g[p];

    // LIF: mem starts at 0; reset uses previous mem; spike from new mem.
    float mem[8];
#pragma unroll
    for (int p = 0; p < 8; p++) mem[p] = 0.f;

    unsigned words[8];
#pragma unroll
    for (int w = 0; w < 8; w++) words[w] = 0u;

    float rsum = 0.f;
#pragma unroll
    for (int t = 0; t < TT; t++) {
        unsigned byte = 0u;
#pragma unroll
        for (int p = 0; p < 8; p++) {
            const float prev = mem[p];
            float m = 0.95f * prev + Iv[p];
            if (prev > thr[p]) m -= thr[p];
            mem[p] = m;
            byte |= ((m > thr[p]) ? 1u : 0u) << p;
        }
        words[t >> 2] |= byte << ((t & 3) * 8);
        rsum += lutR[byte];
    }

    // Temporal branch: conv1 (K=3, SAME) via LUTs, relu, conv2 (1x1), mean.
    const float w2x = c2w[0], w2y = c2w[1], w2z = c2w[2], w2w = c2w[3];
    float tacc = 0.f;
    unsigned prev = 0u;
    unsigned cur = words[0] & 0xffu;
#pragma unroll
    for (int t = 0; t < TT; t++) {
        const unsigned nxt =
            (t < TT - 1) ? ((words[(t + 1) >> 2] >> (((t + 1) & 3) * 8)) & 0xffu) : 0u;
        const float4 a = lut0[prev];
        const float4 b = lut1[cur];
        const float4 c = lut2[nxt];
        const float v0 = a.x + b.x + c.x;
        const float v1 = a.y + b.y + c.y;
        const float v2 = a.z + b.z + c.z;
        const float v3 = a.w + b.w + c.w;
        tacc = fmaf(w2x, fmaxf(v0, 0.f), tacc);
        tacc = fmaf(w2y, fmaxf(v1, 0.f), tacc);
        tacc = fmaf(w2z, fmaxf(v2, 0.f), tacc);
        tacc = fmaf(w2w, fmaxf(v3, 0.f), tacc);
        prev = cur;
        cur = nxt;
    }

    const float rate_dec = rsum * (1.f / TT) + rateB[0];
    const float temp_dec = tacc * (1.f / TT) + c2b[0];

    const float e0 = expf(fusion[0]);
    const float e1 = expf(fusion[1]);
    const float inv = 1.f / (e0 + e1);

    out[cell] = (e0 * inv) * rate_dec + (e1 * inv) * temp_dec;
}

// ---------------------------------------------------------------------------
extern "C" void kernel_launch(void* const* d_in, const int* in_sizes, int n_in,
                              void* d_out, int out_size) {
    (void)in_sizes;
    (void)n_in;
    (void)out_size;
    const float* x       = (const float*)d_in[0];   // [1024,512]
    const float* W_proj  = (const float*)d_in[1];   // [512,2048]
    const float* b_proj  = (const float*)d_in[2];   // [2048]
    const float* thr     = (const float*)d_in[3];   // [8]
    const float* rate_W  = (const float*)d_in[4];   // [8,1]
    const float* rate_b  = (const float*)d_in[5];   // [1]
    const float* conv1_w = (const float*)d_in[6];   // [4,8,3]
    const float* conv1_b = (const float*)d_in[7];   // [4]
    const float* conv2_w = (const float*)d_in[8];   // [1,4,1]
    const float* conv2_b = (const float*)d_in[9];   // [1]
    const float* fusion  = (const float*)d_in[10];  // [2]
    float* out = (float*)d_out;                     // [1024,256]

    dim3 ggrid(GN / 128, GM / 128);                 // (16, 8)
    gemm_kernel<<<ggrid, 256>>>(x, W_proj, b_proj);

    const int cells = GM * DD;                      // 262144
    pop_kernel<<<cells / 256, 256>>>(thr, rate_W, rate_b, conv1_w, conv1_b,
                                     conv2_w, conv2_b, fusion, out);
}

// round 5
// speedup vs baseline: 1.3591x; 1.3591x over previous
#include <cuda_runtime.h>
#include <cuda_fp16.h>

#define GM 1024   // B
#define GK 512    // IN
#define GN 2048   // D*P
#define TT 32     // NUM_STEPS

// Scratch for projected currents I = x @ W_proj + b_proj (8 MB)
__device__ float g_I[GM * GN];

// ---------------------------------------------------------------------------
// 3xTF32 GEMM on tensor cores (mma.sync m16n8k8), 128x128 tile, BK=16.
// C = A[1024,512] @ B[512,2048] + bias, fp32-equivalent accuracy via
// hi/lo split: acc += Ah*Bh + Ah*Bl + Al*Bh.
// ---------------------------------------------------------------------------
__device__ __forceinline__ unsigned f2tf32(float x) {
    unsigned u;
    asm("cvt.rna.tf32.f32 %0, %1;" : "=r"(u) : "f"(x));
    return u;
}

#define MMA_TF32(d, a, b0, b1)                                              \
    asm volatile(                                                           \
        "mma.sync.aligned.m16n8k8.row.col.f32.tf32.tf32.f32 "               \
        "{%0,%1,%2,%3}, {%4,%5,%6,%7}, {%8,%9}, {%0,%1,%2,%3};"             \
        : "+f"(d[0]), "+f"(d[1]), "+f"(d[2]), "+f"(d[3])                    \
        : "r"(a[0]), "r"(a[1]), "r"(a[2]), "r"(a[3]), "r"(b0), "r"(b1))

__global__ __launch_bounds__(256) void gemm_tf32(const float* __restrict__ A,
                                                 const float* __restrict__ B,
                                                 const float* __restrict__ bias) {
    // SMEM fragment-order layouts (tf32 bit patterns):
    // A: frag(kc 0..1, mblk 0..7): 32 lanes x 4 regs.  off=((kc*8+mblk)*32+lane)*4+reg
    // B: pair(kc 0..1, pr 0..7): 32 lanes x 4 = [b0(n0),b1(n0),b0(n1),b1(n1)]
    __shared__ unsigned Ah[2048], Al[2048], Bh[2048], Bl[2048];

    const int tid = threadIdx.x;
    const int lane = tid & 31;
    const int wid = tid >> 5;
    const int mrow = wid & 3;   // 4 warps along M: 32 rows each
    const int ncol = wid >> 2;  // 2 warps along N: 64 cols each
    const int bx = blockIdx.x;  // N tile (16)
    const int by = blockIdx.y;  // M tile (8)

    // global load mapping (2 float4 each for A and B per thread per ktile)
    const int fA0 = tid * 2;
    const int arow0 = fA0 >> 2, ac0 = (fA0 & 3) * 4;
    const int arow1 = (fA0 + 1) >> 2, ac1 = ((fA0 + 1) & 3) * 4;
    const int brow0 = fA0 >> 5, bn0 = (fA0 & 31) * 4;
    const int brow1 = (fA0 + 1) >> 5, bn1 = ((fA0 + 1) & 31) * 4;

    const float* Ag = A + (size_t)(by * 128) * GK;
    const float* Bg = B + bx * 128;

    float acc[2][8][4];
#pragma unroll
    for (int mi = 0; mi < 2; mi++)
#pragma unroll
        for (int ni = 0; ni < 8; ni++)
#pragma unroll
            for (int r = 0; r < 4; r++) acc[mi][ni][r] = 0.f;

    float4 ra0, ra1, rb0, rb1;
    // prefetch ktile 0
    ra0 = *(const float4*)(Ag + (size_t)arow0 * GK + ac0);
    ra1 = *(const float4*)(Ag + (size_t)arow1 * GK + ac1);
    rb0 = *(const float4*)(Bg + (size_t)brow0 * GN + bn0);
    rb1 = *(const float4*)(Bg + (size_t)brow1 * GN + bn1);

    for (int kt = 0; kt < GK / 16; kt++) {
        // ---- STS staged regs (split hi/lo) ----
        {
            const float* va[2] = {&ra0.x, &ra1.x};
            const int rr_[2] = {arow0, arow1};
            const int cc_[2] = {ac0, ac1};
#pragma unroll
            for (int i = 0; i < 2; i++) {
                const int row = rr_[i];
                const int mblk = row >> 4, rrm = row & 15;
#pragma unroll
                for (int j = 0; j < 4; j++) {
                    const int c = cc_[i] + j;
                    const int kc = c >> 3, ccl = c & 7;
                    const int ln = (rrm & 7) * 4 + (ccl & 3);
                    const int rg = (rrm >> 3) + 2 * (ccl >> 2);
                    const int off = ((kc * 8 + mblk) * 32 + ln) * 4 + rg;
                    const float x = va[i][j];
                    const unsigned h = f2tf32(x);
                    Ah[off] = h;
                    Al[off] = f2tf32(x - __uint_as_float(h));
                }
            }
            const float* vb[2] = {&rb0.x, &rb1.x};
            const int kr_[2] = {brow0, brow1};
            const int nn_[2] = {bn0, bn1};
#pragma unroll
            for (int i = 0; i < 2; i++) {
                const int k = kr_[i];
                const int kc = k >> 3, kk = k & 7;
#pragma unroll
                for (int j = 0; j < 4; j++) {
                    const int n = nn_[i] + j;
                    const int nblk = n >> 3, nn = n & 7;
                    const int ln = nn * 4 + (kk & 3);
                    const int pr = nblk >> 1;
                    const int off = ((kc * 8 + pr) * 32 + ln) * 4 + (nblk & 1) * 2 + (kk >> 2);
                    const float x = vb[i][j];
                    const unsigned h = f2tf32(x);
                    Bh[off] = h;
                    Bl[off] = f2tf32(x - __uint_as_float(h));
                }
            }
        }
        __syncthreads();

        // ---- prefetch next ktile ----
        if (kt + 1 < GK / 16) {
            const int k0 = (kt + 1) * 16;
            ra0 = *(const float4*)(Ag + (size_t)arow0 * GK + k0 + ac0);
            ra1 = *(const float4*)(Ag + (size_t)arow1 * GK + k0 + ac1);
            rb0 = *(const float4*)(Bg + (size_t)(k0 + brow0) * GN + bn0);
            rb1 = *(const float4*)(Bg + (size_t)(k0 + brow1) * GN + bn1);
        }

        // ---- compute 2 k-chunks ----
#pragma unroll
        for (int kc = 0; kc < 2; kc++) {
            unsigned afh[2][4], afl[2][4];
#pragma unroll
            for (int mi = 0; mi < 2; mi++) {
                const int base = ((kc * 8 + mrow * 2 + mi) * 32 + lane) * 4;
                *(uint4*)afh[mi] = *(const uint4*)&Ah[base];
                *(uint4*)afl[mi] = *(const uint4*)&Al[base];
            }
            unsigned bfh[4][4], bfl[4][4];
#pragma unroll
            for (int pr = 0; pr < 4; pr++) {
                const int base = ((kc * 8 + ncol * 4 + pr) * 32 + lane) * 4;
                *(uint4*)bfh[pr] = *(const uint4*)&Bh[base];
                *(uint4*)bfl[pr] = *(const uint4*)&Bl[base];
            }
#pragma unroll
            for (int mi = 0; mi < 2; mi++)
#pragma unroll
                for (int ni = 0; ni < 8; ni++) {
                    const int pr = ni >> 1, hf = (ni & 1) * 2;
                    MMA_TF32(acc[mi][ni], afh[mi], bfh[pr][hf], bfh[pr][hf + 1]);
                    MMA_TF32(acc[mi][ni], afh[mi], bfl[pr][hf], bfl[pr][hf + 1]);
                    MMA_TF32(acc[mi][ni], afl[mi], bfh[pr][hf], bfh[pr][hf + 1]);
                }
        }
        __syncthreads();
    }

    // ---- epilogue: add bias, write g_I ----
#pragma unroll
    for (int mi = 0; mi < 2; mi++) {
        const int row0 = by * 128 + mrow * 32 + mi * 16 + (lane >> 2);
#pragma unroll
        for (int ni = 0; ni < 8; ni++) {
            const int col = bx * 128 + ncol * 64 + ni * 8 + (lane & 3) * 2;
            const float b0 = bias[col], b1 = bias[col + 1];
            float2 v0 = make_float2(acc[mi][ni][0] + b0, acc[mi][ni][1] + b1);
            float2 v1 = make_float2(acc[mi][ni][2] + b0, acc[mi][ni][3] + b1);
            *(float2*)&g_I[(size_t)row0 * GN + col] = v0;
            *(float2*)&g_I[(size_t)(row0 + 8) * GN + col] = v1;
        }
    }
}

// ---------------------------------------------------------------------------
// pop_kernel: LIF recurrence + LUT-based rate & temporal branches.
// LUTs fp16-packed (8B/tap-entry) -> halved LDS crossbar traffic.
// ---------------------------------------------------------------------------
struct __align__(8) H2x2 {
    __half2 a, b;
};

__global__ __launch_bounds__(256) void pop_kernel(
    const float* __restrict__ thr_g, const float* __restrict__ rateW,
    const float* __restrict__ rateB, const float* __restrict__ c1w,
    const float* __restrict__ c1b, const float* __restrict__ c2w,
    const float* __restrict__ c2b, const float* __restrict__ fusion,
    float* __restrict__ out) {
    __shared__ H2x2 lutT[3][256];
    __shared__ float lutR[256];

    const int tid = threadIdx.x;
    {
        const int m = tid;
        float s[3][4];
#pragma unroll
        for (int t = 0; t < 3; t++)
#pragma unroll
            for (int c = 0; c < 4; c++) s[t][c] = 0.f;
        float r = 0.f;
#pragma unroll
        for (int p = 0; p < 8; p++) {
            if ((m >> p) & 1) {
                r += rateW[p];
#pragma unroll
                for (int t = 0; t < 3; t++)
#pragma unroll
                    for (int c = 0; c < 4; c++) s[t][c] += c1w[c * 24 + p * 3 + t];
            }
        }
#pragma unroll
        for (int c = 0; c < 4; c++) s[1][c] += c1b[c];  // fold bias into center tap
#pragma unroll
        for (int t = 0; t < 3; t++) {
            H2x2 e;
            e.a = __floats2half2_rn(s[t][0], s[t][1]);
            e.b = __floats2half2_rn(s[t][2], s[t][3]);
            lutT[t][m] = e;
        }
        lutR[m] = r;
    }
    __syncthreads();

    const int cell = blockIdx.x * 256 + tid;

    const float4 i0 = *(const float4*)(g_I + (size_t)cell * 8);
    const float4 i1 = *(const float4*)(g_I + (size_t)cell * 8 + 4);
    float Iv[8] = {i0.x, i0.y, i0.z, i0.w, i1.x, i1.y, i1.z, i1.w};

    float thr[8];
#pragma unroll
    for (int p = 0; p < 8; p++) thr[p] = thr_g[p];

    float mem[8];
    bool spk[8];
#pragma unroll
    for (int p = 0; p < 8; p++) {
        mem[p] = 0.f;
        spk[p] = false;
    }

    unsigned words[8];
#pragma unroll
    for (int w = 0; w < 8; w++) words[w] = 0u;

    float rsum = 0.f;
#pragma unroll
    for (int t = 0; t < TT; t++) {
        unsigned byte = 0u;
#pragma unroll
        for (int p = 0; p < 8; p++) {
            // reset condition == spike of previous step (H(mem_prev - thr))
            float m = fmaf(0.95f, mem[p], Iv[p]) - (spk[p] ? thr[p] : 0.f);
            mem[p] = m;
            const bool s = m > thr[p];
            spk[p] = s;
            byte |= (s ? 1u : 0u) << p;
        }
        words[t >> 2] |= byte << ((t & 3) * 8);
        rsum += lutR[byte];
    }

    const float w2x = c2w[0], w2y = c2w[1], w2z = c2w[2], w2w = c2w[3];
    const __half2 zero2 = __float2half2_rn(0.f);
    float tacc = 0.f;
    unsigned prevb = 0u;
    unsigned curb = words[0] & 0xffu;
#pragma unroll
    for (int t = 0; t < TT; t++) {
        const unsigned nxtb =
            (t < TT - 1) ? ((words[(t + 1) >> 2] >> (((t + 1) & 3) * 8)) & 0xffu) : 0u;
        const H2x2 e0 = lutT[0][prevb];
        const H2x2 e1 = lutT[1][curb];
        const H2x2 e2 = lutT[2][nxtb];
        __half2 s01 = __hadd2(__hadd2(e0.a, e1.a), e2.a);
        __half2 s23 = __hadd2(__hadd2(e0.b, e1.b), e2.b);
        s01 = __hmax2(s01, zero2);
        s23 = __hmax2(s23, zero2);
        const float2 f01 = __half22float2(s01);
        const float2 f23 = __half22float2(s23);
        tacc = fmaf(w2x, f01.x, tacc);
        tacc = fmaf(w2y, f01.y, tacc);
        tacc = fmaf(w2z, f23.x, tacc);
        tacc = fmaf(w2w, f23.y, tacc);
        prevb = curb;
        curb = nxtb;
    }

    const float rate_dec = rsum * (1.f / TT) + rateB[0];
    const float temp_dec = tacc * (1.f / TT) + c2b[0];

    const float e0 = expf(fusion[0]);
    const float e1 = expf(fusion[1]);
    const float inv = 1.f / (e0 + e1);

    out[cell] = (e0 * inv) * rate_dec + (e1 * inv) * temp_dec;
}

// ---------------------------------------------------------------------------
extern "C" void kernel_launch(void* const* d_in, const int* in_sizes, int n_in,
                              void* d_out, int out_size) {
    (void)in_sizes;
    (void)n_in;
    (void)out_size;
    const float* x       = (const float*)d_in[0];
    const float* W_proj  = (const float*)d_in[1];
    const float* b_proj  = (const float*)d_in[2];
    const float* thr     = (const float*)d_in[3];
    const float* rate_W  = (const float*)d_in[4];
    const float* rate_b  = (const float*)d_in[5];
    const float* conv1_w = (const float*)d_in[6];
    const float* conv1_b = (const float*)d_in[7];
    const float* conv2_w = (const float*)d_in[8];
    const float* conv2_b = (const float*)d_in[9];
    const float* fusion  = (const float*)d_in[10];
    float* out = (float*)d_out;

    dim3 ggrid(GN / 128, GM / 128);  // (16, 8)
    gemm_tf32<<<ggrid, 256>>>(x, W_proj, b_proj);

    pop_kernel<<<(GM * 256) / 256, 256>>>(thr, rate_W, rate_b, conv1_w, conv1_b,
                                          conv2_w, conv2_b, fusion, out);
}

// round 9
// speedup vs baseline: 1.4513x; 1.0678x over previous
#include <cuda_runtime.h>

#define GM 1024   // B
#define GK 512    // IN
#define GN 2048   // D*P
#define TT 32     // NUM_STEPS
#define NKB (GK / 8)   // 64 k-blocks of 8

// Scratch buffers
__device__ float g_I[GM * GN];                 // 8 MB
__device__ float g_Ah[NKB * 64 * 128];         // 2 MB  [kb][mb(64)][128]
__device__ float g_Al[NKB * 64 * 128];         // 2 MB
__device__ float g_Bh[NKB * 128 * 128];        // 4 MB  [kb][prg(128)][128]
__device__ float g_Bl[NKB * 128 * 128];        // 4 MB

__device__ __forceinline__ unsigned f2tf32(float x) {
    unsigned u;
    asm("cvt.rna.tf32.f32 %0, %1;" : "=r"(u) : "f"(x));
    return u;
}

// ---------------------------------------------------------------------------
// Prepass A: A[1024,512] fp32 -> tf32 hi/lo in m16k8 fragment order.
// frag elem j = ln*4+rg; forward map: ln=(r&7)*4+(c&3), rg=(r>>3)+2*(c>>2).
// ---------------------------------------------------------------------------
__global__ __launch_bounds__(256) void prep_A(const float* __restrict__ A) {
    __shared__ float tile[16 * 512];
    const int mb = blockIdx.x;  // 0..63 (16-row slab)
    for (int i = threadIdx.x; i < 16 * 512; i += 256) {
        const int r = i >> 9, c = i & 511;
        tile[i] = A[(size_t)(mb * 16 + r) * GK + c];
    }
    __syncthreads();
    for (int f = threadIdx.x; f < NKB * 128; f += 256) {
        const int kb = f >> 7, j = f & 127;
        const int ln = j >> 2, rg = j & 3;
        const int r = (ln >> 2) | ((rg & 1) << 3);
        const int c = (ln & 3) | ((rg & 2) << 1);
        const float v = tile[r * 512 + kb * 8 + c];
        const unsigned h = f2tf32(v);
        const int off = (kb * 64 + mb) * 128 + j;
        g_Ah[off] = __uint_as_float(h);
        g_Al[off] = __uint_as_float(f2tf32(v - __uint_as_float(h)));
    }
}

// ---------------------------------------------------------------------------
// Prepass B: B[512,2048] fp32 -> tf32 hi/lo, n8k8 pair-fragment order.
// pair prg covers n in [prg*16, prg*16+16); j = ln*4+q,
// ln = nn*4+(kk&3); q = 2*(nblk&1) + (kk>>2).
// ---------------------------------------------------------------------------
__global__ __launch_bounds__(256) void prep_B(const float* __restrict__ B) {
    __shared__ float tile[8 * 1024];
    const int kb = blockIdx.x >> 1;
    const int half = blockIdx.x & 1;  // n in [half*1024, +1024)
    for (int i = threadIdx.x; i < 8 * 1024; i += 256) {
        const int r = i >> 10, c = i & 1023;
        tile[i] = B[(size_t)(kb * 8 + r) * GN + half * 1024 + c];
    }
    __syncthreads();
    for (int f = threadIdx.x; f < 64 * 128; f += 256) {
        const int prl = f >> 7, j = f & 127;
        const int ln = j >> 2, q = j & 3;
        const int nn = ln >> 2;
        const int kk = (ln & 3) | ((q & 1) << 2);
        const int nl = prl * 16 + (q >> 1) * 8 + nn;  // col within half
        const float v = tile[kk * 1024 + nl];
        const unsigned h = f2tf32(v);
        const int off = (kb * 128 + half * 64 + prl) * 128 + j;
        g_Bh[off] = __uint_as_float(h);
        g_Bl[off] = __uint_as_float(f2tf32(v - __uint_as_float(h)));
    }
}

// ---------------------------------------------------------------------------
// Main GEMM: cp.async double-buffered fragments -> mma.sync m16n8k8 tf32 x3.
// ---------------------------------------------------------------------------
#define MMA_TF32(d, a, b0, b1)                                              \
    asm volatile(                                                           \
        "mma.sync.aligned.m16n8k8.row.col.f32.tf32.tf32.f32 "               \
        "{%0,%1,%2,%3}, {%4,%5,%6,%7}, {%8,%9}, {%0,%1,%2,%3};"             \
        : "+f"(d[0]), "+f"(d[1]), "+f"(d[2]), "+f"(d[3])                    \
        : "r"(a[0]), "r"(a[1]), "r"(a[2]), "r"(a[3]), "r"(b0), "r"(b1))

__global__ __launch_bounds__(256) void gemm_tf32(const float* __restrict__ bias) {
    // sbuf[stage][region 0=Ah 1=Al 2=Bh 3=Bl][1024 floats]
    __shared__ float sbuf[2][4][1024];

    const int tid = threadIdx.x;
    const int lane = tid & 31;
    const int wid = tid >> 5;
    const int mrow = wid & 3;   // 4 warps along M (32 rows each)
    const int ncol = wid >> 2;  // 2 warps along N (64 cols each)
    const int bx = blockIdx.x;  // N tile (16)
    const int by = blockIdx.y;  // M tile (8)

    // cp.async assignment: region = tid>>6, 4 chunks of 16B each
    const int region = tid >> 6;
    const int l64 = tid & 63;
    const float* src_base[4] = {
        g_Ah + (size_t)(by * 8) * 128, g_Al + (size_t)(by * 8) * 128,
        g_Bh + (size_t)(bx * 8) * 128, g_Bl + (size_t)(bx * 8) * 128};
    const size_t src_kb_stride[4] = {64 * 128, 64 * 128, 128 * 128, 128 * 128};

    float acc[2][8][4];
#pragma unroll
    for (int mi = 0; mi < 2; mi++)
#pragma unroll
        for (int ni = 0; ni < 8; ni++)
#pragma unroll
            for (int r = 0; r < 4; r++) acc[mi][ni][r] = 0.f;

    unsigned sdst_base =
        (unsigned)__cvta_generic_to_shared(&sbuf[0][region][0]) + l64 * 16;

    // issue copy for kb=0 into stage 0
    {
        const float* s = src_base[region] + l64 * 4;
#pragma unroll
        for (int i = 0; i < 4; i++) {
            asm volatile("cp.async.cg.shared.global [%0], [%1], 16;" ::"r"(
                             sdst_base + i * 1024),
                         "l"(s + i * 256));
        }
        asm volatile("cp.async.commit_group;");
    }

    for (int kb = 0; kb < NKB; kb++) {
        const int st = kb & 1;
        if (kb + 1 < NKB) {
            const unsigned d = sdst_base + (st ^ 1) * (4 * 4096);
            const float* s =
                src_base[region] + (size_t)(kb + 1) * src_kb_stride[region] + l64 * 4;
#pragma unroll
            for (int i = 0; i < 4; i++) {
                asm volatile("cp.async.cg.shared.global [%0], [%1], 16;" ::"r"(
                                 d + i * 1024),
                             "l"(s + i * 256));
            }
            asm volatile("cp.async.commit_group;");
            asm volatile("cp.async.wait_group 1;");
        } else {
            asm volatile("cp.async.wait_group 0;");
        }
        __syncthreads();

        // ---- compute from stage st ----
        const float* Ahs = sbuf[st][0];
        const float* Als = sbuf[st][1];
        const float* Bhs = sbuf[st][2];
        const float* Bls = sbuf[st][3];

        unsigned afh[2][4], afl[2][4];
#pragma unroll
        for (int mi = 0; mi < 2; mi++) {
            const int base = ((mrow * 2 + mi) * 32 + lane) * 4;
            *(uint4*)afh[mi] = *(const uint4*)&Ahs[base];
            *(uint4*)afl[mi] = *(const uint4*)&Als[base];
        }
        unsigned bfh[4][4], bfl[4][4];
#pragma unroll
        for (int pr = 0; pr < 4; pr++) {
            const int base = ((ncol * 4 + pr) * 32 + lane) * 4;
            *(uint4*)bfh[pr] = *(const uint4*)&Bhs[base];
            *(uint4*)bfl[pr] = *(const uint4*)&Bls[base];
        }
#pragma unroll
        for (int mi = 0; mi < 2; mi++)
#pragma unroll
            for (int ni = 0; ni < 8; ni++) {
                const int pr = ni >> 1, hf = (ni & 1) * 2;
                MMA_TF32(acc[mi][ni], afh[mi], bfh[pr][hf], bfh[pr][hf + 1]);
                MMA_TF32(acc[mi][ni], afh[mi], bfl[pr][hf], bfl[pr][hf + 1]);
                MMA_TF32(acc[mi][ni], afl[mi], bfh[pr][hf], bfh[pr][hf + 1]);
            }
        __syncthreads();
    }

    // ---- epilogue: add bias, write g_I (layout proven in R5) ----
#pragma unroll
    for (int mi = 0; mi < 2; mi++) {
        const int row0 = by * 128 + mrow * 32 + mi * 16 + (lane >> 2);
#pragma unroll
        for (int ni = 0; ni < 8; ni++) {
            const int col = bx * 128 + ncol * 64 + ni * 8 + (lane & 3) * 2;
            const float b0 = bias[col], b1 = bias[col + 1];
            float2 v0 = make_float2(acc[mi][ni][0] + b0, acc[mi][ni][1] + b1);
            float2 v1 = make_float2(acc[mi][ni][2] + b0, acc[mi][ni][3] + b1);
            *(float2*)&g_I[(size_t)row0 * GN + col] = v0;
            *(float2*)&g_I[(size_t)(row0 + 8) * GN + col] = v1;
        }
    }
}

// ---------------------------------------------------------------------------
// pop_kernel: LIF (R5-proven) + fp32 float4 LUTs (R1-proven accuracy).
// ---------------------------------------------------------------------------
__global__ __launch_bounds__(256) void pop_kernel(
    const float* __restrict__ thr_g, const float* __restrict__ rateW,
    const float* __restrict__ rateB, const float* __restrict__ c1w,
    const float* __restrict__ c1b, const float* __restrict__ c2w,
    const float* __restrict__ c2b, const float* __restrict__ fusion,
    float* __restrict__ out) {
    __shared__ float4 lut0[256], lut1[256], lut2[256];
    __shared__ float lutR[256];

    const int tid = threadIdx.x;
    {
        const int m = tid;
        float s[3][4];
#pragma unroll
        for (int t = 0; t < 3; t++)
#pragma unroll
            for (int c = 0; c < 4; c++) s[t][c] = 0.f;
        float r = 0.f;
#pragma unroll
        for (int p = 0; p < 8; p++) {
            if ((m >> p) & 1) {
                r += rateW[p];
#pragma unroll
                for (int t = 0; t < 3; t++)
#pragma unroll
                    for (int c = 0; c < 4; c++) s[t][c] += c1w[c * 24 + p * 3 + t];
            }
        }
#pragma unroll
        for (int c = 0; c < 4; c++) s[1][c] += c1b[c];  // bias into center tap
        lut0[m] = make_float4(s[0][0], s[0][1], s[0][2], s[0][3]);
        lut1[m] = make_float4(s[1][0], s[1][1], s[1][2], s[1][3]);
        lut2[m] = make_float4(s[2][0], s[2][1], s[2][2], s[2][3]);
        lutR[m] = r;
    }
    __syncthreads();

    const int cell = blockIdx.x * 256 + tid;

    const float4 i0 = *(const float4*)(g_I + (size_t)cell * 8);
    const float4 i1 = *(const float4*)(g_I + (size_t)cell * 8 + 4);
    float Iv[8] = {i0.x, i0.y, i0.z, i0.w, i1.x, i1.y, i1.z, i1.w};

    float thr[8];
#pragma unroll
    for (int p = 0; p < 8; p++) thr[p] = thr_g[p];

    float mem[8];
    bool spk[8];
#pragma unroll
    for (int p = 0; p < 8; p++) {
        mem[p] = 0.f;
        spk[p] = false;
    }

    unsigned words[8];
#pragma unroll
    for (int w = 0; w < 8; w++) words[w] = 0u;

    float rsum = 0.f;
#pragma unroll
    for (int t = 0; t < TT; t++) {
        unsigned byte = 0u;
#pragma unroll
        for (int p = 0; p < 8; p++) {
            // reset condition == previous step's spike (H(mem_prev - thr))
            float m = fmaf(0.95f, mem[p], Iv[p]) - (spk[p] ? thr[p] : 0.f);
            mem[p] = m;
            const bool s = m > thr[p];
            spk[p] = s;
            byte |= (s ? 1u : 0u) << p;
        }
        words[t >> 2] |= byte << ((t & 3) * 8);
        rsum += lutR[byte];
    }

    const float w2x = c2w[0], w2y = c2w[1], w2z = c2w[2], w2w = c2w[3];
    float tacc = 0.f;
    unsigned prevb = 0u;
    unsigned curb = words[0] & 0xffu;
#pragma unroll
    for (int t = 0; t < TT; t++) {
        const unsigned nxtb =
            (t < TT - 1) ? ((words[(t + 1) >> 2] >> (((t + 1) & 3) * 8)) & 0xffu) : 0u;
        const float4 a = lut0[prevb];
        const float4 b = lut1[curb];
        const float4 c = lut2[nxtb];
        tacc = fmaf(w2x, fmaxf(a.x + b.x + c.x, 0.f), tacc);
        tacc = fmaf(w2y, fmaxf(a.y + b.y + c.y, 0.f), tacc);
        tacc = fmaf(w2z, fmaxf(a.z + b.z + c.z, 0.f), tacc);
        tacc = fmaf(w2w, fmaxf(a.w + b.w + c.w, 0.f), tacc);
        prevb = curb;
        curb = nxtb;
    }

    const float rate_dec = rsum * (1.f / TT) + rateB[0];
    const float temp_dec = tacc * (1.f / TT) + c2b[0];

    const float e0 = expf(fusion[0]);
    const float e1 = expf(fusion[1]);
    const float inv = 1.f / (e0 + e1);

    out[cell] = (e0 * inv) * rate_dec + (e1 * inv) * temp_dec;
}

// ---------------------------------------------------------------------------
extern "C" void kernel_launch(void* const* d_in, const int* in_sizes, int n_in,
                              void* d_out, int out_size) {
    (void)in_sizes;
    (void)n_in;
    (void)out_size;
    const float* x       = (const float*)d_in[0];
    const float* W_proj  = (const float*)d_in[1];
    const float* b_proj  = (const float*)d_in[2];
    const float* thr     = (const float*)d_in[3];
    const float* rate_W  = (const float*)d_in[4];
    const float* rate_b  = (const float*)d_in[5];
    const float* conv1_w = (const float*)d_in[6];
    const float* conv1_b = (const float*)d_in[7];
    const float* conv2_w = (const float*)d_in[8];
    const float* conv2_b = (const float*)d_in[9];
    const float* fusion  = (const float*)d_in[10];
    float* out = (float*)d_out;

    prep_A<<<64, 256>>>(x);
    prep_B<<<128, 256>>>(W_proj);

    dim3 ggrid(GN / 128, GM / 128);  // (16, 8)
    gemm_tf32<<<ggrid, 256>>>(b_proj);

    pop_kernel<<<(GM * 256) / 256, 256>>>(thr, rate_W, rate_b, conv1_w, conv1_b,
                                          conv2_w, conv2_b, fusion, out);
}

// round 11
// speedup vs baseline: 1.5521x; 1.0695x over previous
#include <cuda_runtime.h>
#include <cuda_fp16.h>

#define GM 1024   // B
#define GK 512    // IN
#define GN 2048   // D*P
#define TT 32     // NUM_STEPS
#define NKB (GK / 8)   // 64 k-blocks of 8

// Scratch buffers
__device__ float g_I[GM * GN];                 // 8 MB
__device__ float g_Ah[NKB * 64 * 128];         // 2 MB  [kb][mb(64)][128]
__device__ float g_Al[NKB * 64 * 128];         // 2 MB
__device__ float g_Bh[NKB * 128 * 128];        // 4 MB  [kb][prg(128)][128]
__device__ float g_Bl[NKB * 128 * 128];        // 4 MB

__device__ __forceinline__ unsigned f2tf32(float x) {
    unsigned u;
    asm("cvt.rna.tf32.f32 %0, %1;" : "=r"(u) : "f"(x));
    return u;
}

// ---------------------------------------------------------------------------
// Prepass A: A[1024,512] fp32 -> tf32 hi/lo in m16k8 fragment order.
// ---------------------------------------------------------------------------
__global__ __launch_bounds__(256) void prep_A(const float* __restrict__ A) {
    __shared__ float tile[16 * 512];
    const int mb = blockIdx.x;  // 0..63 (16-row slab)
    for (int i = threadIdx.x; i < 16 * 512; i += 256) {
        const int r = i >> 9, c = i & 511;
        tile[i] = A[(size_t)(mb * 16 + r) * GK + c];
    }
    __syncthreads();
    for (int f = threadIdx.x; f < NKB * 128; f += 256) {
        const int kb = f >> 7, j = f & 127;
        const int ln = j >> 2, rg = j & 3;
        const int r = (ln >> 2) | ((rg & 1) << 3);
        const int c = (ln & 3) | ((rg & 2) << 1);
        const float v = tile[r * 512 + kb * 8 + c];
        const unsigned h = f2tf32(v);
        const int off = (kb * 64 + mb) * 128 + j;
        g_Ah[off] = __uint_as_float(h);
        g_Al[off] = __uint_as_float(f2tf32(v - __uint_as_float(h)));
    }
}

// ---------------------------------------------------------------------------
// Prepass B: B[512,2048] fp32 -> tf32 hi/lo, n8k8 pair-fragment order.
// ---------------------------------------------------------------------------
__global__ __launch_bounds__(256) void prep_B(const float* __restrict__ B) {
    __shared__ float tile[8 * 1024];
    const int kb = blockIdx.x >> 1;
    const int half = blockIdx.x & 1;  // n in [half*1024, +1024)
    for (int i = threadIdx.x; i < 8 * 1024; i += 256) {
        const int r = i >> 10, c = i & 1023;
        tile[i] = B[(size_t)(kb * 8 + r) * GN + half * 1024 + c];
    }
    __syncthreads();
    for (int f = threadIdx.x; f < 64 * 128; f += 256) {
        const int prl = f >> 7, j = f & 127;
        const int ln = j >> 2, q = j & 3;
        const int nn = ln >> 2;
        const int kk = (ln & 3) | ((q & 1) << 2);
        const int nl = prl * 16 + (q >> 1) * 8 + nn;  // col within half
        const float v = tile[kk * 1024 + nl];
        const unsigned h = f2tf32(v);
        const int off = (kb * 128 + half * 64 + prl) * 128 + j;
        g_Bh[off] = __uint_as_float(h);
        g_Bl[off] = __uint_as_float(f2tf32(v - __uint_as_float(h)));
    }
}

// ---------------------------------------------------------------------------
// Main GEMM: cp.async double-buffered fragments -> mma.sync m16n8k8 tf32 x4
// (full split product: AhBh + AhBl + AlBh + AlBl -> fp32-equivalent).
// ---------------------------------------------------------------------------
#define MMA_TF32(d, a, b0, b1)                                              \
    asm volatile(                                                           \
        "mma.sync.aligned.m16n8k8.row.col.f32.tf32.tf32.f32 "               \
        "{%0,%1,%2,%3}, {%4,%5,%6,%7}, {%8,%9}, {%0,%1,%2,%3};"             \
        : "+f"(d[0]), "+f"(d[1]), "+f"(d[2]), "+f"(d[3])                    \
        : "r"(a[0]), "r"(a[1]), "r"(a[2]), "r"(a[3]), "r"(b0), "r"(b1))

__global__ __launch_bounds__(256) void gemm_tf32(const float* __restrict__ bias) {
    // sbuf[stage][region 0=Ah 1=Al 2=Bh 3=Bl][1024 floats]
    __shared__ float sbuf[2][4][1024];

    const int tid = threadIdx.x;
    const int lane = tid & 31;
    const int wid = tid >> 5;
    const int mrow = wid & 3;   // 4 warps along M (32 rows each)
    const int ncol = wid >> 2;  // 2 warps along N (64 cols each)
    const int bx = blockIdx.x;  // N tile (16)
    const int by = blockIdx.y;  // M tile (8)

    const int region = tid >> 6;
    const int l64 = tid & 63;
    const float* src_base[4] = {
        g_Ah + (size_t)(by * 8) * 128, g_Al + (size_t)(by * 8) * 128,
        g_Bh + (size_t)(bx * 8) * 128, g_Bl + (size_t)(bx * 8) * 128};
    const size_t src_kb_stride[4] = {64 * 128, 64 * 128, 128 * 128, 128 * 128};

    float acc[2][8][4];
#pragma unroll
    for (int mi = 0; mi < 2; mi++)
#pragma unroll
        for (int ni = 0; ni < 8; ni++)
#pragma unroll
            for (int r = 0; r < 4; r++) acc[mi][ni][r] = 0.f;

    unsigned sdst_base =
        (unsigned)__cvta_generic_to_shared(&sbuf[0][region][0]) + l64 * 16;

    {
        const float* s = src_base[region] + l64 * 4;
#pragma unroll
        for (int i = 0; i < 4; i++) {
            asm volatile("cp.async.cg.shared.global [%0], [%1], 16;" ::"r"(
                             sdst_base + i * 1024),
                         "l"(s + i * 256));
        }
        asm volatile("cp.async.commit_group;");
    }

    for (int kb = 0; kb < NKB; kb++) {
        const int st = kb & 1;
        if (kb + 1 < NKB) {
            const unsigned d = sdst_base + (st ^ 1) * (4 * 4096);
            const float* s =
                src_base[region] + (size_t)(kb + 1) * src_kb_stride[region] + l64 * 4;
#pragma unroll
            for (int i = 0; i < 4; i++) {
                asm volatile("cp.async.cg.shared.global [%0], [%1], 16;" ::"r"(
                                 d + i * 1024),
                             "l"(s + i * 256));
            }
            asm volatile("cp.async.commit_group;");
            asm volatile("cp.async.wait_group 1;");
        } else {
            asm volatile("cp.async.wait_group 0;");
        }
        __syncthreads();

        const float* Ahs = sbuf[st][0];
        const float* Als = sbuf[st][1];
        const float* Bhs = sbuf[st][2];
        const float* Bls = sbuf[st][3];

        unsigned afh[2][4], afl[2][4];
#pragma unroll
        for (int mi = 0; mi < 2; mi++) {
            const int base = ((mrow * 2 + mi) * 32 + lane) * 4;
            *(uint4*)afh[mi] = *(const uint4*)&Ahs[base];
            *(uint4*)afl[mi] = *(const uint4*)&Als[base];
        }
        unsigned bfh[4][4], bfl[4][4];
#pragma unroll
        for (int pr = 0; pr < 4; pr++) {
            const int base = ((ncol * 4 + pr) * 32 + lane) * 4;
            *(uint4*)bfh[pr] = *(const uint4*)&Bhs[base];
            *(uint4*)bfl[pr] = *(const uint4*)&Bls[base];
        }
#pragma unroll
        for (int mi = 0; mi < 2; mi++)
#pragma unroll
            for (int ni = 0; ni < 8; ni++) {
                const int pr = ni >> 1, hf = (ni & 1) * 2;
                MMA_TF32(acc[mi][ni], afh[mi], bfh[pr][hf], bfh[pr][hf + 1]);
                MMA_TF32(acc[mi][ni], afh[mi], bfl[pr][hf], bfl[pr][hf + 1]);
                MMA_TF32(acc[mi][ni], afl[mi], bfh[pr][hf], bfh[pr][hf + 1]);
                MMA_TF32(acc[mi][ni], afl[mi], bfl[pr][hf], bfl[pr][hf + 1]);
            }
        __syncthreads();
    }

#pragma unroll
    for (int mi = 0; mi < 2; mi++) {
        const int row0 = by * 128 + mrow * 32 + mi * 16 + (lane >> 2);
#pragma unroll
        for (int ni = 0; ni < 8; ni++) {
            const int col = bx * 128 + ncol * 64 + ni * 8 + (lane & 3) * 2;
            const float b0 = bias[col], b1 = bias[col + 1];
            float2 v0 = make_float2(acc[mi][ni][0] + b0, acc[mi][ni][1] + b1);
            float2 v1 = make_float2(acc[mi][ni][2] + b0, acc[mi][ni][3] + b1);
            *(float2*)&g_I[(size_t)row0 * GN + col] = v0;
            *(float2*)&g_I[(size_t)(row0 + 8) * GN + col] = v1;
        }
    }
}

// ---------------------------------------------------------------------------
// pop_kernel: fused LIF + temporal conv in ONE loop.
// fp16 LUTs (R5-measured 12us faster than fp32); tap-history pipeline:
//   v(t-1) = lut0[b_{t-2}] + lut1[b_{t-1}] + lut2[b_t]  (lut0/2[0] == 0)
// ---------------------------------------------------------------------------
struct __align__(8) H2x2 {
    __half2 a, b;
};
__device__ __forceinline__ H2x2 h2x2_zero() {
    H2x2 z;
    z.a = __float2half2_rn(0.f);
    z.b = __float2half2_rn(0.f);
    return z;
}

__global__ __launch_bounds__(256) void pop_kernel(
    const float* __restrict__ thr_g, const float* __restrict__ rateW,
    const float* __restrict__ rateB, const float* __restrict__ c1w,
    const float* __restrict__ c1b, const float* __restrict__ c2w,
    const float* __restrict__ c2b, const float* __restrict__ fusion,
    float* __restrict__ out) {
    __shared__ H2x2 lutT[3][256];
    __shared__ float lutR[256];

    const int tid = threadIdx.x;
    {
        const int m = tid;
        float s[3][4];
#pragma unroll
        for (int t = 0; t < 3; t++)
#pragma unroll
            for (int c = 0; c < 4; c++) s[t][c] = 0.f;
        float r = 0.f;
#pragma unroll
        for (int p = 0; p < 8; p++) {
            if ((m >> p) & 1) {
                r += rateW[p];
#pragma unroll
                for (int t = 0; t < 3; t++)
#pragma unroll
                    for (int c = 0; c < 4; c++) s[t][c] += c1w[c * 24 + p * 3 + t];
            }
        }
#pragma unroll
        for (int c = 0; c < 4; c++) s[1][c] += c1b[c];  // bias into center tap
#pragma unroll
        for (int t = 0; t < 3; t++) {
            H2x2 e;
            e.a = __floats2half2_rn(s[t][0], s[t][1]);
            e.b = __floats2half2_rn(s[t][2], s[t][3]);
            lutT[t][m] = e;
        }
        lutR[m] = r;
    }
    __syncthreads();

    const int cell = blockIdx.x * 256 + tid;

    const float4 i0 = *(const float4*)(g_I + (size_t)cell * 8);
    const float4 i1 = *(const float4*)(g_I + (size_t)cell * 8 + 4);
    float Iv[8] = {i0.x, i0.y, i0.z, i0.w, i1.x, i1.y, i1.z, i1.w};

    float thr[8];
#pragma unroll
    for (int p = 0; p < 8; p++) thr[p] = thr_g[p];

    float mem[8];
    bool spk[8];
#pragma unroll
    for (int p = 0; p < 8; p++) {
        mem[p] = 0.f;
        spk[p] = false;
    }

    const float w2x = c2w[0], w2y = c2w[1], w2z = c2w[2], w2w = c2w[3];
    const __half2 zero2 = __float2half2_rn(0.f);

    float rsum = 0.f;
    float tacc = 0.f;
    // tap history: L0 from t-2, L0 from t-1 (staging), L1 from t-1
    H2x2 a0p2 = h2x2_zero(), a0p1 = h2x2_zero(), a1p1 = h2x2_zero();

#pragma unroll
    for (int t = 0; t < TT; t++) {
        unsigned byte = 0u;
#pragma unroll
        for (int p = 0; p < 8; p++) {
            // reset condition == previous step's spike (H(mem_prev - thr))
            float m = fmaf(0.95f, mem[p], Iv[p]) - (spk[p] ? thr[p] : 0.f);
            mem[p] = m;
            const bool s = m > thr[p];
            spk[p] = s;
            byte |= (s ? 1u : 0u) << p;
        }
        const H2x2 L0 = lutT[0][byte];
        const H2x2 L1 = lutT[1][byte];
        const H2x2 L2 = lutT[2][byte];
        rsum += lutR[byte];

        if (t > 0) {
            __half2 s01 = __hadd2(__hadd2(a0p2.a, a1p1.a), L2.a);
            __half2 s23 = __hadd2(__hadd2(a0p2.b, a1p1.b), L2.b);
            s01 = __hmax2(s01, zero2);
            s23 = __hmax2(s23, zero2);
            const float2 f01 = __half22float2(s01);
            const float2 f23 = __half22float2(s23);
            tacc = fmaf(w2x, f01.x, tacc);
            tacc = fmaf(w2y, f01.y, tacc);
            tacc = fmaf(w2z, f23.x, tacc);
            tacc = fmaf(w2w, f23.y, tacc);
        }
        a0p2 = a0p1;
        a0p1 = L0;
        a1p1 = L1;
    }
    // tail: v(TT-1) = L0[b_{TT-2}] + L1[b_{TT-1}] + L2[pad]=0
    {
        __half2 s01 = __hadd2(a0p2.a, a1p1.a);
        __half2 s23 = __hadd2(a0p2.b, a1p1.b);
        s01 = __hmax2(s01, zero2);
        s23 = __hmax2(s23, zero2);
        const float2 f01 = __half22float2(s01);
        const float2 f23 = __half22float2(s23);
        tacc = fmaf(w2x, f01.x, tacc);
        tacc = fmaf(w2y, f01.y, tacc);
        tacc = fmaf(w2z, f23.x, tacc);
        tacc = fmaf(w2w, f23.y, tacc);
    }

    const float rate_dec = rsum * (1.f / TT) + rateB[0];
    const float temp_dec = tacc * (1.f / TT) + c2b[0];

    const float e0 = expf(fusion[0]);
    const float e1 = expf(fusion[1]);
    const float inv = 1.f / (e0 + e1);

    out[cell] = (e0 * inv) * rate_dec + (e1 * inv) * temp_dec;
}

// ---------------------------------------------------------------------------
extern "C" void kernel_launch(void* const* d_in, const int* in_sizes, int n_in,
                              void* d_out, int out_size) {
    (void)in_sizes;
    (void)n_in;
    (void)out_size;
    const float* x       = (const float*)d_in[0];
    const float* W_proj  = (const float*)d_in[1];
    const float* b_proj  = (const float*)d_in[2];
    const float* thr     = (const float*)d_in[3];
    const float* rate_W  = (const float*)d_in[4];
    const float* rate_b  = (const float*)d_in[5];
    const float* conv1_w = (const float*)d_in[6];
    const float* conv1_b = (const float*)d_in[7];
    const float* conv2_w = (const float*)d_in[8];
    const float* conv2_b = (const float*)d_in[9];
    const float* fusion  = (const float*)d_in[10];
    float* out = (float*)d_out;

    prep_A<<<64, 256>>>(x);
    prep_B<<<128, 256>>>(W_proj);

    dim3 ggrid(GN / 128, GM / 128);  // (16, 8)
    gemm_tf32<<<ggrid, 256>>>(b_proj);

    pop_kernel<<<(GM * 256) / 256, 256>>>(thr, rate_W, rate_b, conv1_w, conv1_b,
                                          conv2_w, conv2_b, fusion, out);
}

// round 13
// speedup vs baseline: 1.6837x; 1.0848x over previous
#include <cuda_runtime.h>
#include <cuda_fp16.h>

#define GM 1024   // B
#define GK 512    // IN
#define GN 2048   // D*P
#define TT 32     // NUM_STEPS
#define NKB (GK / 8)   // 64 k-blocks of 8

// Scratch buffers
__device__ float g_I[GM * GN];                 // 8 MB
__device__ float g_Ah[NKB * 64 * 128];         // 2 MB  [kb][mb(64)][128]
__device__ float g_Al[NKB * 64 * 128];         // 2 MB
__device__ float g_Bh[NKB * 128 * 128];        // 4 MB  [kb][prg(128)][128]
__device__ float g_Bl[NKB * 128 * 128];        // 4 MB

__device__ __forceinline__ unsigned f2tf32(float x) {
    unsigned u;
    asm("cvt.rna.tf32.f32 %0, %1;" : "=r"(u) : "f"(x));
    return u;
}

// ---------------------------------------------------------------------------
// Prepass A: A[1024,512] fp32 -> tf32 hi/lo in m16k8 fragment order.
// ---------------------------------------------------------------------------
__global__ __launch_bounds__(256) void prep_A(const float* __restrict__ A) {
    __shared__ float tile[16 * 512];
    const int mb = blockIdx.x;  // 0..63 (16-row slab)
    for (int i = threadIdx.x; i < 16 * 512; i += 256) {
        const int r = i >> 9, c = i & 511;
        tile[i] = A[(size_t)(mb * 16 + r) * GK + c];
    }
    __syncthreads();
    for (int f = threadIdx.x; f < NKB * 128; f += 256) {
        const int kb = f >> 7, j = f & 127;
        const int ln = j >> 2, rg = j & 3;
        const int r = (ln >> 2) | ((rg & 1) << 3);
        const int c = (ln & 3) | ((rg & 2) << 1);
        const float v = tile[r * 512 + kb * 8 + c];
        const unsigned h = f2tf32(v);
        const int off = (kb * 64 + mb) * 128 + j;
        g_Ah[off] = __uint_as_float(h);
        g_Al[off] = __uint_as_float(f2tf32(v - __uint_as_float(h)));
    }
}

// ---------------------------------------------------------------------------
// Prepass B: B[512,2048] fp32 -> tf32 hi/lo, n8k8 pair-fragment order.
// ---------------------------------------------------------------------------
__global__ __launch_bounds__(256) void prep_B(const float* __restrict__ B) {
    __shared__ float tile[8 * 1024];
    const int kb = blockIdx.x >> 1;
    const int half = blockIdx.x & 1;  // n in [half*1024, +1024)
    for (int i = threadIdx.x; i < 8 * 1024; i += 256) {
        const int r = i >> 10, c = i & 1023;
        tile[i] = B[(size_t)(kb * 8 + r) * GN + half * 1024 + c];
    }
    __syncthreads();
    for (int f = threadIdx.x; f < 64 * 128; f += 256) {
        const int prl = f >> 7, j = f & 127;
        const int ln = j >> 2, q = j & 3;
        const int nn = ln >> 2;
        const int kk = (ln & 3) | ((q & 1) << 2);
        const int nl = prl * 16 + (q >> 1) * 8 + nn;  // col within half
        const float v = tile[kk * 1024 + nl];
        const unsigned h = f2tf32(v);
        const int off = (kb * 128 + half * 64 + prl) * 128 + j;
        g_Bh[off] = __uint_as_float(h);
        g_Bl[off] = __uint_as_float(f2tf32(v - __uint_as_float(h)));
    }
}

// ---------------------------------------------------------------------------
// Main GEMM: cp.async double-buffered fragments -> mma.sync m16n8k8 tf32 x3
// (3-term split: AhBh + AhBl + AlBh; R5/R9-proven numerics).
// ---------------------------------------------------------------------------
#define MMA_TF32(d, a, b0, b1)                                              \
    asm volatile(                                                           \
        "mma.sync.aligned.m16n8k8.row.col.f32.tf32.tf32.f32 "               \
        "{%0,%1,%2,%3}, {%4,%5,%6,%7}, {%8,%9}, {%0,%1,%2,%3};"             \
        : "+f"(d[0]), "+f"(d[1]), "+f"(d[2]), "+f"(d[3])                    \
        : "r"(a[0]), "r"(a[1]), "r"(a[2]), "r"(a[3]), "r"(b0), "r"(b1))

__global__ __launch_bounds__(256) void gemm_tf32(const float* __restrict__ bias) {
    // sbuf[stage][region 0=Ah 1=Al 2=Bh 3=Bl][1024 floats]
    __shared__ float sbuf[2][4][1024];

    const int tid = threadIdx.x;
    const int lane = tid & 31;
    const int wid = tid >> 5;
    const int mrow = wid & 3;   // 4 warps along M (32 rows each)
    const int ncol = wid >> 2;  // 2 warps along N (64 cols each)
    const int bx = blockIdx.x;  // N tile (16)
    const int by = blockIdx.y;  // M tile (8)

    const int region = tid >> 6;
    const int l64 = tid & 63;
    const float* src_base[4] = {
        g_Ah + (size_t)(by * 8) * 128, g_Al + (size_t)(by * 8) * 128,
        g_Bh + (size_t)(bx * 8) * 128, g_Bl + (size_t)(bx * 8) * 128};
    const size_t src_kb_stride[4] = {64 * 128, 64 * 128, 128 * 128, 128 * 128};

    float acc[2][8][4];
#pragma unroll
    for (int mi = 0; mi < 2; mi++)
#pragma unroll
        for (int ni = 0; ni < 8; ni++)
#pragma unroll
            for (int r = 0; r < 4; r++) acc[mi][ni][r] = 0.f;

    unsigned sdst_base =
        (unsigned)__cvta_generic_to_shared(&sbuf[0][region][0]) + l64 * 16;

    {
        const float* s = src_base[region] + l64 * 4;
#pragma unroll
        for (int i = 0; i < 4; i++) {
            asm volatile("cp.async.cg.shared.global [%0], [%1], 16;" ::"r"(
                             sdst_base + i * 1024),
                         "l"(s + i * 256));
        }
        asm volatile("cp.async.commit_group;");
    }

    for (int kb = 0; kb < NKB; kb++) {
        const int st = kb & 1;
        if (kb + 1 < NKB) {
            const unsigned d = sdst_base + (st ^ 1) * (4 * 4096);
            const float* s =
                src_base[region] + (size_t)(kb + 1) * src_kb_stride[region] + l64 * 4;
#pragma unroll
            for (int i = 0; i < 4; i++) {
                asm volatile("cp.async.cg.shared.global [%0], [%1], 16;" ::"r"(
                                 d + i * 1024),
                             "l"(s + i * 256));
            }
            asm volatile("cp.async.commit_group;");
            asm volatile("cp.async.wait_group 1;");
        } else {
            asm volatile("cp.async.wait_group 0;");
        }
        __syncthreads();

        const float* Ahs = sbuf[st][0];
        const float* Als = sbuf[st][1];
        const float* Bhs = sbuf[st][2];
        const float* Bls = sbuf[st][3];

        unsigned afh[2][4], afl[2][4];
#pragma unroll
        for (int mi = 0; mi < 2; mi++) {
            const int base = ((mrow * 2 + mi) * 32 + lane) * 4;
            *(uint4*)afh[mi] = *(const uint4*)&Ahs[base];
            *(uint4*)afl[mi] = *(const uint4*)&Als[base];
        }
        unsigned bfh[4][4], bfl[4][4];
#pragma unroll
        for (int pr = 0; pr < 4; pr++) {
            const int base = ((ncol * 4 + pr) * 32 + lane) * 4;
            *(uint4*)bfh[pr] = *(const uint4*)&Bhs[base];
            *(uint4*)bfl[pr] = *(const uint4*)&Bls[base];
        }
#pragma unroll
        for (int mi = 0; mi < 2; mi++)
#pragma unroll
            for (int ni = 0; ni < 8; ni++) {
                const int pr = ni >> 1, hf = (ni & 1) * 2;
                MMA_TF32(acc[mi][ni], afh[mi], bfh[pr][hf], bfh[pr][hf + 1]);
                MMA_TF32(acc[mi][ni], afh[mi], bfl[pr][hf], bfl[pr][hf + 1]);
                MMA_TF32(acc[mi][ni], afl[mi], bfh[pr][hf], bfh[pr][hf + 1]);
            }
        __syncthreads();
    }

#pragma unroll
    for (int mi = 0; mi < 2; mi++) {
        const int row0 = by * 128 + mrow * 32 + mi * 16 + (lane >> 2);
#pragma unroll
        for (int ni = 0; ni < 8; ni++) {
            const int col = bx * 128 + ncol * 64 + ni * 8 + (lane & 3) * 2;
            const float b0 = bias[col], b1 = bias[col + 1];
            float2 v0 = make_float2(acc[mi][ni][0] + b0, acc[mi][ni][1] + b1);
            float2 v1 = make_float2(acc[mi][ni][2] + b0, acc[mi][ni][3] + b1);
            *(float2*)&g_I[(size_t)row0 * GN + col] = v0;
            *(float2*)&g_I[(size_t)(row0 + 8) * GN + col] = v1;
        }
    }
}

// ---------------------------------------------------------------------------
// pop_kernel: fused LIF + temporal conv in ONE loop (R11-measured 27.4us).
// fp16 LUTs; tap-history pipeline:
//   v(t-1) = lut0[b_{t-2}] + lut1[b_{t-1}] + lut2[b_t]  (lut0/2[0] == 0)
// ---------------------------------------------------------------------------
struct __align__(8) H2x2 {
    __half2 a, b;
};
__device__ __forceinline__ H2x2 h2x2_zero() {
    H2x2 z;
    z.a = __float2half2_rn(0.f);
    z.b = __float2half2_rn(0.f);
    return z;
}

__global__ __launch_bounds__(256) void pop_kernel(
    const float* __restrict__ thr_g, const float* __restrict__ rateW,
    const float* __restrict__ rateB, const float* __restrict__ c1w,
    const float* __restrict__ c1b, const float* __restrict__ c2w,
    const float* __restrict__ c2b, const float* __restrict__ fusion,
    float* __restrict__ out) {
    __shared__ H2x2 lutT[3][256];
    __shared__ float lutR[256];

    const int tid = threadIdx.x;
    {
        const int m = tid;
        float s[3][4];
#pragma unroll
        for (int t = 0; t < 3; t++)
#pragma unroll
            for (int c = 0; c < 4; c++) s[t][c] = 0.f;
        float r = 0.f;
#pragma unroll
        for (int p = 0; p < 8; p++) {
            if ((m >> p) & 1) {
                r += rateW[p];
#pragma unroll
                for (int t = 0; t < 3; t++)
#pragma unroll
                    for (int c = 0; c < 4; c++) s[t][c] += c1w[c * 24 + p * 3 + t];
            }
        }
#pragma unroll
        for (int c = 0; c < 4; c++) s[1][c] += c1b[c];  // bias into center tap
#pragma unroll
        for (int t = 0; t < 3; t++) {
            H2x2 e;
            e.a = __floats2half2_rn(s[t][0], s[t][1]);
            e.b = __floats2half2_rn(s[t][2], s[t][3]);
            lutT[t][m] = e;
        }
        lutR[m] = r;
    }
    __syncthreads();

    const int cell = blockIdx.x * 256 + tid;

    const float4 i0 = *(const float4*)(g_I + (size_t)cell * 8);
    const float4 i1 = *(const float4*)(g_I + (size_t)cell * 8 + 4);
    float Iv[8] = {i0.x, i0.y, i0.z, i0.w, i1.x, i1.y, i1.z, i1.w};

    float thr[8];
#pragma unroll
    for (int p = 0; p < 8; p++) thr[p] = thr_g[p];

    float mem[8];
    bool spk[8];
#pragma unroll
    for (int p = 0; p < 8; p++) {
        mem[p] = 0.f;
        spk[p] = false;
    }

    const float w2x = c2w[0], w2y = c2w[1], w2z = c2w[2], w2w = c2w[3];
    const __half2 zero2 = __float2half2_rn(0.f);

    float rsum = 0.f;
    float tacc = 0.f;
    // tap history: L0 from t-2, L0 from t-1 (staging), L1 from t-1
    H2x2 a0p2 = h2x2_zero(), a0p1 = h2x2_zero(), a1p1 = h2x2_zero();

#pragma unroll
    for (int t = 0; t < TT; t++) {
        unsigned byte = 0u;
#pragma unroll
        for (int p = 0; p < 8; p++) {
            // reset condition == previous step's spike (H(mem_prev - thr))
            float m = fmaf(0.95f, mem[p], Iv[p]) - (spk[p] ? thr[p] : 0.f);
            mem[p] = m;
            const bool s = m > thr[p];
            spk[p] = s;
            byte |= (s ? 1u : 0u) << p;
        }
        const H2x2 L0 = lutT[0][byte];
        const H2x2 L1 = lutT[1][byte];
        const H2x2 L2 = lutT[2][byte];
        rsum += lutR[byte];

        if (t > 0) {
            __half2 s01 = __hadd2(__hadd2(a0p2.a, a1p1.a), L2.a);
            __half2 s23 = __hadd2(__hadd2(a0p2.b, a1p1.b), L2.b);
            s01 = __hmax2(s01, zero2);
            s23 = __hmax2(s23, zero2);
            const float2 f01 = __half22float2(s01);
            const float2 f23 = __half22float2(s23);
            tacc = fmaf(w2x, f01.x, tacc);
            tacc = fmaf(w2y, f01.y, tacc);
            tacc = fmaf(w2z, f23.x, tacc);
            tacc = fmaf(w2w, f23.y, tacc);
        }
        a0p2 = a0p1;
        a0p1 = L0;
        a1p1 = L1;
    }
    // tail: v(TT-1) = L0[b_{TT-2}] + L1[b_{TT-1}] + L2[pad]=0
    {
        __half2 s01 = __hadd2(a0p2.a, a1p1.a);
        __half2 s23 = __hadd2(a0p2.b, a1p1.b);
        s01 = __hmax2(s01, zero2);
        s23 = __hmax2(s23, zero2);
        const float2 f01 = __half22float2(s01);
        const float2 f23 = __half22float2(s23);
        tacc = fmaf(w2x, f01.x, tacc);
        tacc = fmaf(w2y, f01.y, tacc);
        tacc = fmaf(w2z, f23.x, tacc);
        tacc = fmaf(w2w, f23.y, tacc);
    }

    const float rate_dec = rsum * (1.f / TT) + rateB[0];
    const float temp_dec = tacc * (1.f / TT) + c2b[0];

    const float e0 = expf(fusion[0]);
    const float e1 = expf(fusion[1]);
    const float inv = 1.f / (e0 + e1);

    out[cell] = (e0 * inv) * rate_dec + (e1 * inv) * temp_dec;
}

// ---------------------------------------------------------------------------
extern "C" void kernel_launch(void* const* d_in, const int* in_sizes, int n_in,
                              void* d_out, int out_size) {
    (void)in_sizes;
    (void)n_in;
    (void)out_size;
    const float* x       = (const float*)d_in[0];
    const float* W_proj  = (const float*)d_in[1];
    const float* b_proj  = (const float*)d_in[2];
    const float* thr     = (const float*)d_in[3];
    const float* rate_W  = (const float*)d_in[4];
    const float* rate_b  = (const float*)d_in[5];
    const float* conv1_w = (const float*)d_in[6];
    const float* conv1_b = (const float*)d_in[7];
    const float* conv2_w = (const float*)d_in[8];
    const float* conv2_b = (const float*)d_in[9];
    const float* fusion  = (const float*)d_in[10];
    float* out = (float*)d_out;

    prep_A<<<64, 256>>>(x);
    prep_B<<<128, 256>>>(W_proj);

    dim3 ggrid(GN / 128, GM / 128);  // (16, 8)
    gemm_tf32<<<ggrid, 256>>>(b_proj);

    pop_kernel<<<(GM * 256) / 256, 256>>>(thr, rate_W, rate_b, conv1_w, conv1_b,
                                          conv2_w, conv2_b, fusion, out);
}

// round 15
// speedup vs baseline: 1.7182x; 1.0205x over previous
#include <cuda_runtime.h>
#include <cuda_fp16.h>
#include <string.h>

#define GM 1024   // B
#define GK 512    // IN
#define GN 2048   // D*P
#define TT 32     // NUM_STEPS
#define NKB (GK / 8)   // 64 k-blocks of 8

// Scratch buffers
__device__ float g_I[GM * GN];                 // 8 MB
__device__ float g_Ah[NKB * 64 * 128];         // 2 MB  [kb][mb(64)][128]
__device__ float g_Al[NKB * 64 * 128];         // 2 MB
__device__ float g_Bh[NKB * 128 * 128];        // 4 MB  [kb][prg(128)][128]
__device__ float g_Bl[NKB * 128 * 128];        // 4 MB

__device__ __forceinline__ unsigned f2tf32(float x) {
    unsigned u;
    asm("cvt.rna.tf32.f32 %0, %1;" : "=r"(u) : "f"(x));
    return u;
}

// bit-casts between __half2 and unsigned (register moves, no real intrinsics)
__device__ __forceinline__ unsigned h2_as_u32(__half2 h) {
    unsigned u;
    memcpy(&u, &h, 4);
    return u;
}
__device__ __forceinline__ __half2 u32_as_h2(unsigned u) {
    __half2 h;
    memcpy(&h, &u, 4);
    return h;
}

// ---------------------------------------------------------------------------
// Prepass A: A[1024,512] fp32 -> tf32 hi/lo in m16k8 fragment order.
// ---------------------------------------------------------------------------
__global__ __launch_bounds__(256) void prep_A(const float* __restrict__ A) {
    __shared__ float tile[16 * 512];
    const int mb = blockIdx.x;  // 0..63 (16-row slab)
    for (int i = threadIdx.x; i < 16 * 512; i += 256) {
        const int r = i >> 9, c = i & 511;
        tile[i] = A[(size_t)(mb * 16 + r) * GK + c];
    }
    __syncthreads();
    for (int f = threadIdx.x; f < NKB * 128; f += 256) {
        const int kb = f >> 7, j = f & 127;
        const int ln = j >> 2, rg = j & 3;
        const int r = (ln >> 2) | ((rg & 1) << 3);
        const int c = (ln & 3) | ((rg & 2) << 1);
        const float v = tile[r * 512 + kb * 8 + c];
        const unsigned h = f2tf32(v);
        const int off = (kb * 64 + mb) * 128 + j;
        g_Ah[off] = __uint_as_float(h);
        g_Al[off] = __uint_as_float(f2tf32(v - __uint_as_float(h)));
    }
}

// ---------------------------------------------------------------------------
// Prepass B: B[512,2048] fp32 -> tf32 hi/lo, n8k8 pair-fragment order.
// ---------------------------------------------------------------------------
__global__ __launch_bounds__(256) void prep_B(const float* __restrict__ B) {
    __shared__ float tile[8 * 1024];
    const int kb = blockIdx.x >> 1;
    const int half = blockIdx.x & 1;  // n in [half*1024, +1024)
    for (int i = threadIdx.x; i < 8 * 1024; i += 256) {
        const int r = i >> 10, c = i & 1023;
        tile[i] = B[(size_t)(kb * 8 + r) * GN + half * 1024 + c];
    }
    __syncthreads();
    for (int f = threadIdx.x; f < 64 * 128; f += 256) {
        const int prl = f >> 7, j = f & 127;
        const int ln = j >> 2, q = j & 3;
        const int nn = ln >> 2;
        const int kk = (ln & 3) | ((q & 1) << 2);
        const int nl = prl * 16 + (q >> 1) * 8 + nn;  // col within half
        const float v = tile[kk * 1024 + nl];
        const unsigned h = f2tf32(v);
        const int off = (kb * 128 + half * 64 + prl) * 128 + j;
        g_Bh[off] = __uint_as_float(h);
        g_Bl[off] = __uint_as_float(f2tf32(v - __uint_as_float(h)));
    }
}

// ---------------------------------------------------------------------------
// Main GEMM: 3-stage cp.async pipeline, ONE __syncthreads per ktile.
// mma.sync m16n8k8 tf32 x3 (AhBh + AhBl + AlBh; R5/R13-proven numerics).
// ---------------------------------------------------------------------------
#define MMA_TF32(d, a, b0, b1)                                              \
    asm volatile(                                                           \
        "mma.sync.aligned.m16n8k8.row.col.f32.tf32.tf32.f32 "               \
        "{%0,%1,%2,%3}, {%4,%5,%6,%7}, {%8,%9}, {%0,%1,%2,%3};"             \
        : "+f"(d[0]), "+f"(d[1]), "+f"(d[2]), "+f"(d[3])                    \
        : "r"(a[0]), "r"(a[1]), "r"(a[2]), "r"(a[3]), "r"(b0), "r"(b1))

__global__ __launch_bounds__(256) void gemm_tf32(const float* __restrict__ bias) {
    // sbuf[stage 0..2][region 0=Ah 1=Al 2=Bh 3=Bl][1024 floats] = 48KB
    __shared__ float sbuf[3][4][1024];

    const int tid = threadIdx.x;
    const int lane = tid & 31;
    const int wid = tid >> 5;
    const int mrow = wid & 3;   // 4 warps along M (32 rows each)
    const int ncol = wid >> 2;  // 2 warps along N (64 cols each)
    const int bx = blockIdx.x;  // N tile (16)
    const int by = blockIdx.y;  // M tile (8)

    const int region = tid >> 6;
    const int l64 = tid & 63;
    const float* src_base[4] = {
        g_Ah + (size_t)(by * 8) * 128, g_Al + (size_t)(by * 8) * 128,
        g_Bh + (size_t)(bx * 8) * 128, g_Bl + (size_t)(bx * 8) * 128};
    const size_t src_kb_stride[4] = {64 * 128, 64 * 128, 128 * 128, 128 * 128};

    float acc[2][8][4];
#pragma unroll
    for (int mi = 0; mi < 2; mi++)
#pragma unroll
        for (int ni = 0; ni < 8; ni++)
#pragma unroll
            for (int r = 0; r < 4; r++) acc[mi][ni][r] = 0.f;

    const unsigned sdst0 =
        (unsigned)__cvta_generic_to_shared(&sbuf[0][region][0]) + l64 * 16;
    const unsigned stage_bytes = 4 * 4096;  // 16KB per stage

    // prologue: issue kb=0 (stage 0) and kb=1 (stage 1)
#pragma unroll
    for (int pk = 0; pk < 2; pk++) {
        const unsigned d = sdst0 + pk * stage_bytes;
        const float* s = src_base[region] + (size_t)pk * src_kb_stride[region] + l64 * 4;
#pragma unroll
        for (int i = 0; i < 4; i++) {
            asm volatile("cp.async.cg.shared.global [%0], [%1], 16;" ::"r"(
                             d + i * 1024),
                         "l"(s + i * 256));
        }
        asm volatile("cp.async.commit_group;");
    }

    int st = 0;  // kb % 3
    for (int kb = 0; kb < NKB; kb++) {
        if (kb + 1 < NKB) {
            asm volatile("cp.async.wait_group 1;");
        } else {
            asm volatile("cp.async.wait_group 0;");
        }
        __syncthreads();

        // issue kb+2 into stage (kb+2)%3 — disjoint from compute (kb%3) and
        // in-flight ((kb+1)%3); prior read of that stage fenced by the sync.
        if (kb + 2 < NKB) {
            int st2 = st + 2;
            if (st2 >= 3) st2 -= 3;
            const unsigned d = sdst0 + st2 * stage_bytes;
            const float* s =
                src_base[region] + (size_t)(kb + 2) * src_kb_stride[region] + l64 * 4;
#pragma unroll
            for (int i = 0; i < 4; i++) {
                asm volatile("cp.async.cg.shared.global [%0], [%1], 16;" ::"r"(
                                 d + i * 1024),
                             "l"(s + i * 256));
            }
            asm volatile("cp.async.commit_group;");
        }

        // ---- compute from stage st ----
        const float* Ahs = sbuf[st][0];
        const float* Als = sbuf[st][1];
        const float* Bhs = sbuf[st][2];
        const float* Bls = sbuf[st][3];

        unsigned afh[2][4], afl[2][4];
#pragma unroll
        for (int mi = 0; mi < 2; mi++) {
            const int base = ((mrow * 2 + mi) * 32 + lane) * 4;
            *(uint4*)afh[mi] = *(const uint4*)&Ahs[base];
            *(uint4*)afl[mi] = *(const uint4*)&Als[base];
        }
        unsigned bfh[4][4], bfl[4][4];
#pragma unroll
        for (int pr = 0; pr < 4; pr++) {
            const int base = ((ncol * 4 + pr) * 32 + lane) * 4;
            *(uint4*)bfh[pr] = *(const uint4*)&Bhs[base];
            *(uint4*)bfl[pr] = *(const uint4*)&Bls[base];
        }
#pragma unroll
        for (int mi = 0; mi < 2; mi++)
#pragma unroll
            for (int ni = 0; ni < 8; ni++) {
                const int pr = ni >> 1, hf = (ni & 1) * 2;
                MMA_TF32(acc[mi][ni], afh[mi], bfh[pr][hf], bfh[pr][hf + 1]);
                MMA_TF32(acc[mi][ni], afh[mi], bfl[pr][hf], bfl[pr][hf + 1]);
                MMA_TF32(acc[mi][ni], afl[mi], bfh[pr][hf], bfh[pr][hf + 1]);
            }

        if (++st == 3) st = 0;
    }

#pragma unroll
    for (int mi = 0; mi < 2; mi++) {
        const int row0 = by * 128 + mrow * 32 + mi * 16 + (lane >> 2);
#pragma unroll
        for (int ni = 0; ni < 8; ni++) {
            const int col = bx * 128 + ncol * 64 + ni * 8 + (lane & 3) * 2;
            const float b0 = bias[col], b1 = bias[col + 1];
            float2 v0 = make_float2(acc[mi][ni][0] + b0, acc[mi][ni][1] + b1);
            float2 v1 = make_float2(acc[mi][ni][2] + b0, acc[mi][ni][3] + b1);
            *(float2*)&g_I[(size_t)row0 * GN + col] = v0;
            *(float2*)&g_I[(size_t)(row0 + 8) * GN + col] = v1;
        }
    }
}

// ---------------------------------------------------------------------------
// pop_kernel: fused LIF + temporal conv; LUTs packed into 2x 16B tables so
// each timestep does 2 LDS.128 (same index) instead of 3 LDS.64 + 1 LDS.32.
//   lut01[m] = {L0.a, L0.b, L1.a, L1.b}   lut2r[m] = {L2.a, L2.b, rate, 0}
// ---------------------------------------------------------------------------
struct __align__(8) H2x2 {
    __half2 a, b;
};
__device__ __forceinline__ H2x2 h2x2_zero() {
    H2x2 z;
    z.a = __float2half2_rn(0.f);
    z.b = __float2half2_rn(0.f);
    return z;
}

__global__ __launch_bounds__(256) void pop_kernel(
    const float* __restrict__ thr_g, const float* __restrict__ rateW,
    const float* __restrict__ rateB, const float* __restrict__ c1w,
    const float* __restrict__ c1b, const float* __restrict__ c2w,
    const float* __restrict__ c2b, const float* __restrict__ fusion,
    float* __restrict__ out) {
    __shared__ uint4 lut01[256];
    __shared__ uint4 lut2r[256];

    const int tid = threadIdx.x;
    {
        const int m = tid;
        float s[3][4];
#pragma unroll
        for (int t = 0; t < 3; t++)
#pragma unroll
            for (int c = 0; c < 4; c++) s[t][c] = 0.f;
        float r = 0.f;
#pragma unroll
        for (int p = 0; p < 8; p++) {
            if ((m >> p) & 1) {
                r += rateW[p];
#pragma unroll
                for (int t = 0; t < 3; t++)
#pragma unroll
                    for (int c = 0; c < 4; c++) s[t][c] += c1w[c * 24 + p * 3 + t];
            }
        }
#pragma unroll
        for (int c = 0; c < 4; c++) s[1][c] += c1b[c];  // bias into center tap
        uint4 e01, e2r;
        e01.x = h2_as_u32(__floats2half2_rn(s[0][0], s[0][1]));
        e01.y = h2_as_u32(__floats2half2_rn(s[0][2], s[0][3]));
        e01.z = h2_as_u32(__floats2half2_rn(s[1][0], s[1][1]));
        e01.w = h2_as_u32(__floats2half2_rn(s[1][2], s[1][3]));
        e2r.x = h2_as_u32(__floats2half2_rn(s[2][0], s[2][1]));
        e2r.y = h2_as_u32(__floats2half2_rn(s[2][2], s[2][3]));
        e2r.z = __float_as_uint(r);
        e2r.w = 0u;
        lut01[m] = e01;
        lut2r[m] = e2r;
    }
    __syncthreads();

    const int cell = blockIdx.x * 256 + tid;

    const float4 i0 = *(const float4*)(g_I + (size_t)cell * 8);
    const float4 i1 = *(const float4*)(g_I + (size_t)cell * 8 + 4);
    float Iv[8] = {i0.x, i0.y, i0.z, i0.w, i1.x, i1.y, i1.z, i1.w};

    float thr[8];
#pragma unroll
    for (int p = 0; p < 8; p++) thr[p] = thr_g[p];

    float mem[8];
    bool spk[8];
#pragma unroll
    for (int p = 0; p < 8; p++) {
        mem[p] = 0.f;
        spk[p] = false;
    }

    const float w2x = c2w[0], w2y = c2w[1], w2z = c2w[2], w2w = c2w[3];
    const __half2 zero2 = __float2half2_rn(0.f);

    float rsum = 0.f;
    float tacc = 0.f;
    // tap history: L0 from t-2, L0 from t-1 (staging), L1 from t-1
    H2x2 a0p2 = h2x2_zero(), a0p1 = h2x2_zero(), a1p1 = h2x2_zero();

#pragma unroll
    for (int t = 0; t < TT; t++) {
        unsigned byte = 0u;
#pragma unroll
        for (int p = 0; p < 8; p++) {
            // reset condition == previous step's spike (H(mem_prev - thr))
            float m = fmaf(0.95f, mem[p], Iv[p]) - (spk[p] ? thr[p] : 0.f);
            mem[p] = m;
            const bool s = m > thr[p];
            spk[p] = s;
            byte |= (s ? 1u : 0u) << p;
        }
        const uint4 e01 = lut01[byte];
        const uint4 e2r = lut2r[byte];
        H2x2 L0, L1, L2;
        L0.a = u32_as_h2(e01.x);
        L0.b = u32_as_h2(e01.y);
        L1.a = u32_as_h2(e01.z);
        L1.b = u32_as_h2(e01.w);
        L2.a = u32_as_h2(e2r.x);
        L2.b = u32_as_h2(e2r.y);
        rsum += __uint_as_float(e2r.z);

        if (t > 0) {
            __half2 s01 = __hadd2(__hadd2(a0p2.a, a1p1.a), L2.a);
            __half2 s23 = __hadd2(__hadd2(a0p2.b, a1p1.b), L2.b);
            s01 = __hmax2(s01, zero2);
            s23 = __hmax2(s23, zero2);
            const float2 f01 = __half22float2(s01);
            const float2 f23 = __half22float2(s23);
            tacc = fmaf(w2x, f01.x, tacc);
            tacc = fmaf(w2y, f01.y, tacc);
            tacc = fmaf(w2z, f23.x, tacc);
            tacc = fmaf(w2w, f23.y, tacc);
        }
        a0p2 = a0p1;
        a0p1 = L0;
        a1p1 = L1;
    }
    // tail: v(TT-1) = L0[b_{TT-2}] + L1[b_{TT-1}] + L2[pad]=0
    {
        __half2 s01 = __hadd2(a0p2.a, a1p1.a);
        __half2 s23 = __hadd2(a0p2.b, a1p1.b);
        s01 = __hmax2(s01, zero2);
        s23 = __hmax2(s23, zero2);
        const float2 f01 = __half22float2(s01);
        const float2 f23 = __half22float2(s23);
        tacc = fmaf(w2x, f01.x, tacc);
        tacc = fmaf(w2y, f01.y, tacc);
        tacc = fmaf(w2z, f23.x, tacc);
        tacc = fmaf(w2w, f23.y, tacc);
    }

    const float rate_dec = rsum * (1.f / TT) + rateB[0];
    const float temp_dec = tacc * (1.f / TT) + c2b[0];

    const float e0 = expf(fusion[0]);
    const float e1 = expf(fusion[1]);
    const float inv = 1.f / (e0 + e1);

    out[cell] = (e0 * inv) * rate_dec + (e1 * inv) * temp_dec;
}

// ---------------------------------------------------------------------------
extern "C" void kernel_launch(void* const* d_in, const int* in_sizes, int n_in,
                              void* d_out, int out_size) {
    (void)in_sizes;
    (void)n_in;
    (void)out_size;
    const float* x       = (const float*)d_in[0];
    const float* W_proj  = (const float*)d_in[1];
    const float* b_proj  = (const float*)d_in[2];
    const float* thr     = (const float*)d_in[3];
    const float* rate_W  = (const float*)d_in[4];
    const float* rate_b  = (const float*)d_in[5];
    const float* conv1_w = (const float*)d_in[6];
    const float* conv1_b = (const float*)d_in[7];
    const float* conv2_w = (const float*)d_in[8];
    const float* conv2_b = (const float*)d_in[9];
    const float* fusion  = (const float*)d_in[10];
    float* out = (float*)d_out;

    prep_A<<<64, 256>>>(x);
    prep_B<<<128, 256>>>(W_proj);

    dim3 ggrid(GN / 128, GM / 128);  // (16, 8)
    gemm_tf32<<<ggrid, 256>>>(b_proj);

    pop_kernel<<<(GM * 256) / 256, 256>>>(thr, rate_W, rate_b, conv1_w, conv1_b,
                                          conv2_w, conv2_b, fusion, out);
}